// round 17
// baseline (speedup 1.0000x reference)
#include <cuda_runtime.h>
#include <cuda_bf16.h>
#include <cuda_fp16.h>
#include <cstdint>

#define N_NODES 100000
#define N_EDGES 1600000
#define F_IN    128
#define F_HID   128
#define F_OUT   64

#define NB_G  ((N_NODES + 127) / 128)          // 782
#define NB_E4 ((N_EDGES / 4 + 255) / 256)      // 1563
#define NB_N  ((N_NODES + 255) / 256)          // 391

typedef unsigned long long u64;

__device__ __forceinline__ uint32_t packbf(__nv_bfloat16 a, __nv_bfloat16 b) {
    return ((uint32_t)__bfloat16_as_ushort(b) << 16) | __bfloat16_as_ushort(a);
}
__device__ __forceinline__ void mma_bf16(float* d, const uint32_t* a, const uint32_t* b) {
    asm volatile(
        "mma.sync.aligned.m16n8k16.row.col.f32.bf16.bf16.f32 "
        "{%0,%1,%2,%3}, {%4,%5,%6,%7}, {%8,%9}, {%0,%1,%2,%3};"
        : "+f"(d[0]), "+f"(d[1]), "+f"(d[2]), "+f"(d[3])
        : "r"(a[0]), "r"(a[1]), "r"(a[2]), "r"(a[3]), "r"(b[0]), "r"(b[1]));
}

// ---------------- static device scratch ----------------
__device__ int   g_cnt[N_NODES];     // zero-init at load; k_offsets re-zeroes
__device__ int   g_off[N_NODES];     // range start (NOT monotone across nodes)
__device__ int   g_cur[N_NODES];     // fill cursor; after fill == range end
__device__ int   g_total;
__device__ int   g_srcs[N_EDGES];
__device__ float g_dinv[N_NODES];
__device__ __align__(16) __half g_hs1h[N_NODES * F_HID];
__device__ __align__(16) float  g_agg1[N_NODES * F_HID];
__device__ __align__(16) __half g_hs2h[N_NODES * F_OUT];

// ---------------- CSR: histogram (+ reset allocator) ----------------
__global__ void k_hist(const int* __restrict__ ei) {
    if (blockIdx.x == 0 && threadIdx.x == 0) g_total = 0;
    int e4 = blockIdx.x * blockDim.x + threadIdx.x;
    if (e4 * 4 < N_EDGES) {
        int4 d = *(const int4*)&ei[N_EDGES + e4 * 4];
        if ((unsigned)d.x < N_NODES) atomicAdd(&g_cnt[d.x], 1);
        if ((unsigned)d.y < N_NODES) atomicAdd(&g_cnt[d.y], 1);
        if ((unsigned)d.z < N_NODES) atomicAdd(&g_cnt[d.z], 1);
        if ((unsigned)d.w < N_NODES) atomicAdd(&g_cnt[d.w], 1);
    }
}

// ---------------- CSR: parallel range allocation ----------------
__global__ void k_offsets() {
    const int i    = blockIdx.x * 256 + threadIdx.x;
    const int lane = threadIdx.x & 31;
    const int wid  = threadIdx.x >> 5;
    int c = (i < N_NODES) ? g_cnt[i] : 0;
    int pre = c;
#pragma unroll
    for (int d = 1; d < 32; d <<= 1) {
        int v = __shfl_up_sync(0xFFFFFFFFu, pre, d);
        if (lane >= d) pre += v;
    }
    __shared__ int wsum[8], woff[8], base;
    if (lane == 31) wsum[wid] = pre;
    __syncthreads();
    if (threadIdx.x == 0) {
        int r = 0;
#pragma unroll
        for (int q = 0; q < 8; q++) { woff[q] = r; r += wsum[q]; }
        base = atomicAdd(&g_total, r);
    }
    __syncthreads();
    if (i < N_NODES) {
        int ofs = base + woff[wid] + pre - c;
        g_off[i]  = ofs;
        g_cur[i]  = ofs;
        g_dinv[i] = rsqrtf((float)(c + 1));
        g_cnt[i]  = 0;
    }
}

// ================= fused: CSR fill (8 edges/thread) + layer-1 split-bf16 GEMM =========
// Grid = NB_G (782). Fill is a fire-and-forget atomic prologue overlapping the GEMM.
__global__ __launch_bounds__(256) void k_mma1_fill(
    const float* __restrict__ A, const int* __restrict__ ei,
    const float* __restrict__ W1g)
{
    // ---------- fill slice: 2 x int4 per thread (782*512 >= 400000 e4-items) ----------
    {
        int b = blockIdx.x * 512 + threadIdx.x;
#pragma unroll
        for (int rep = 0; rep < 2; rep++) {
            int e4 = b + rep * 256;
            if (e4 * 4 < N_EDGES) {
                int4 s = *(const int4*)&ei[e4 * 4];
                int4 d = *(const int4*)&ei[N_EDGES + e4 * 4];
                if ((unsigned)d.x < N_NODES && (unsigned)s.x < N_NODES)
                    g_srcs[atomicAdd(&g_cur[d.x], 1)] = s.x;
                if ((unsigned)d.y < N_NODES && (unsigned)s.y < N_NODES)
                    g_srcs[atomicAdd(&g_cur[d.y], 1)] = s.y;
                if ((unsigned)d.z < N_NODES && (unsigned)s.z < N_NODES)
                    g_srcs[atomicAdd(&g_cur[d.z], 1)] = s.z;
                if ((unsigned)d.w < N_NODES && (unsigned)s.w < N_NODES)
                    g_srcs[atomicAdd(&g_cur[d.w], 1)] = s.w;
            }
        }
    }

    // ---------- layer-1 GEMM tile ----------
    constexpr int NW = F_HID;
    constexpr int K  = 128;
    constexpr int KC = 32;
    constexpr int SA = KC + 8;
    constexpr int SW = K + 8;
    constexpr int WN = NW / 4;        // 32
    constexpr int NF = WN / 8;        // 4
    constexpr int OFF_AH = 0;
    constexpr int OFF_AL = 128 * SA * 2;
    constexpr int OFF_WH = 2 * 128 * SA * 2;
    constexpr int OFF_WL = OFF_WH + NW * SW * 2;

    extern __shared__ __align__(16) char sm[];
    const int tid  = threadIdx.x;
    const int wid  = tid >> 5;
    const int lane = tid & 31;
    const int mw   = wid >> 2;
    const int nw   = wid & 3;
    const int rowBase = blockIdx.x * 128;

    for (int i = tid; i < NW * (K / 2); i += 256) {
        int n  = i >> 6;
        int k2 = i & 63;
        float v0 = W1g[(2 * k2)     * F_HID + n];
        float v1 = W1g[(2 * k2 + 1) * F_HID + n];
        __nv_bfloat16 h0 = __float2bfloat16(v0), h1 = __float2bfloat16(v1);
        *(uint32_t*)(sm + OFF_WH + (n * SW + 2 * k2) * 2) = packbf(h0, h1);
        *(uint32_t*)(sm + OFF_WL + (n * SW + 2 * k2) * 2) =
            packbf(__float2bfloat16(v0 - __bfloat162float(h0)),
                   __float2bfloat16(v1 - __bfloat162float(h1)));
    }

    float acc[4][NF][4];
#pragma unroll
    for (int mf = 0; mf < 4; mf++)
#pragma unroll
        for (int nf = 0; nf < NF; nf++)
#pragma unroll
            for (int j = 0; j < 4; j++) acc[mf][nf][j] = 0.f;

    const int arow  = tid >> 1;
    const int ahalf = tid & 1;
    const int grow  = rowBase + arow;
    const bool aok  = grow < N_NODES;

    for (int kc = 0; kc < K; kc += KC) {
        {
            const float4* src = (const float4*)&A[(size_t)(aok ? grow : 0) * K + kc + ahalf * 16];
#pragma unroll
            for (int i = 0; i < 4; i++) {
                float4 v = aok ? src[i] : make_float4(0.f, 0.f, 0.f, 0.f);
                __nv_bfloat16 hx = __float2bfloat16(v.x), hy = __float2bfloat16(v.y);
                __nv_bfloat16 hz = __float2bfloat16(v.z), hw = __float2bfloat16(v.w);
                int col = ahalf * 16 + i * 4;
                *(uint32_t*)(sm + OFF_AH + (arow * SA + col) * 2)     = packbf(hx, hy);
                *(uint32_t*)(sm + OFF_AH + (arow * SA + col + 2) * 2) = packbf(hz, hw);
                *(uint32_t*)(sm + OFF_AL + (arow * SA + col) * 2) =
                    packbf(__float2bfloat16(v.x - __bfloat162float(hx)),
                           __float2bfloat16(v.y - __bfloat162float(hy)));
                *(uint32_t*)(sm + OFF_AL + (arow * SA + col + 2) * 2) =
                    packbf(__float2bfloat16(v.z - __bfloat162float(hz)),
                           __float2bfloat16(v.w - __bfloat162float(hw)));
            }
        }
        __syncthreads();

#pragma unroll
        for (int ks = 0; ks < KC / 16; ks++) {
            const int k0 = ks * 16;
            uint32_t bh[NF][2], bl[NF][2];
#pragma unroll
            for (int nf = 0; nf < NF; nf++) {
                int n0 = nw * WN + nf * 8 + (lane >> 2);
                int bc = kc + k0 + (lane & 3) * 2;
                bh[nf][0] = *(const uint32_t*)(sm + OFF_WH + (n0 * SW + bc) * 2);
                bh[nf][1] = *(const uint32_t*)(sm + OFF_WH + (n0 * SW + bc + 8) * 2);
                bl[nf][0] = *(const uint32_t*)(sm + OFF_WL + (n0 * SW + bc) * 2);
                bl[nf][1] = *(const uint32_t*)(sm + OFF_WL + (n0 * SW + bc + 8) * 2);
            }
#pragma unroll
            for (int mf = 0; mf < 4; mf++) {
                int r0 = mw * 64 + mf * 16 + (lane >> 2);
                int ac = k0 + (lane & 3) * 2;
                uint32_t ah[4], al[4];
                ah[0] = *(const uint32_t*)(sm + OFF_AH + ((r0)     * SA + ac) * 2);
                ah[1] = *(const uint32_t*)(sm + OFF_AH + ((r0 + 8) * SA + ac) * 2);
                ah[2] = *(const uint32_t*)(sm + OFF_AH + ((r0)     * SA + ac + 8) * 2);
                ah[3] = *(const uint32_t*)(sm + OFF_AH + ((r0 + 8) * SA + ac + 8) * 2);
                al[0] = *(const uint32_t*)(sm + OFF_AL + ((r0)     * SA + ac) * 2);
                al[1] = *(const uint32_t*)(sm + OFF_AL + ((r0 + 8) * SA + ac) * 2);
                al[2] = *(const uint32_t*)(sm + OFF_AL + ((r0)     * SA + ac + 8) * 2);
                al[3] = *(const uint32_t*)(sm + OFF_AL + ((r0 + 8) * SA + ac + 8) * 2);
#pragma unroll
                for (int nf = 0; nf < NF; nf++) {
                    mma_bf16(acc[mf][nf], ah, bh[nf]);
                    mma_bf16(acc[mf][nf], ah, bl[nf]);
                    mma_bf16(acc[mf][nf], al, bh[nf]);
                }
            }
        }
        __syncthreads();
    }

#pragma unroll
    for (int mf = 0; mf < 4; mf++) {
        int r0 = rowBase + mw * 64 + mf * 16 + (lane >> 2);
        int r1 = r0 + 8;
        float dv0 = (r0 < N_NODES) ? g_dinv[r0] : 0.f;
        float dv1 = (r1 < N_NODES) ? g_dinv[r1] : 0.f;
#pragma unroll
        for (int nf = 0; nf < NF; nf++) {
            int col = nw * WN + nf * 8 + (lane & 3) * 2;
            if (r0 < N_NODES)
                *(__half2*)&g_hs1h[(size_t)r0 * NW + col] =
                    __floats2half2_rn(acc[mf][nf][0] * dv0, acc[mf][nf][1] * dv0);
            if (r1 < N_NODES)
                *(__half2*)&g_hs1h[(size_t)r1 * NW + col] =
                    __floats2half2_rn(acc[mf][nf][2] * dv1, acc[mf][nf][3] * dv1);
        }
    }
}

// ================= layer-2 GEMM: split-bf16 mma.sync (NW=64), fp16 output =================
__global__ __launch_bounds__(256) void k_mma2(const float* __restrict__ W2g) {
    constexpr int NW = F_OUT;         // 64
    constexpr int K  = 128;
    constexpr int KC = 32;
    constexpr int SA = KC + 8;
    constexpr int SW = K + 8;
    constexpr int WN = NW / 4;        // 16
    constexpr int NF = WN / 8;        // 2
    constexpr int OFF_AH = 0;
    constexpr int OFF_AL = 128 * SA * 2;
    constexpr int OFF_WH = 2 * 128 * SA * 2;
    constexpr int OFF_WL = OFF_WH + NW * SW * 2;

    extern __shared__ __align__(16) char sm[];
    const float* A = g_agg1;
    const int tid  = threadIdx.x;
    const int wid  = tid >> 5;
    const int lane = tid & 31;
    const int mw   = wid >> 2;
    const int nw   = wid & 3;
    const int rowBase = blockIdx.x * 128;

    // W2 split/transpose: gmem [k=128][n=64] fp32 -> smem [n][k] bf16 hi/lo
    for (int i = tid; i < NW * (K / 2); i += 256) {
        int n  = i >> 6;
        int k2 = i & 63;
        float v0 = W2g[(2 * k2)     * F_OUT + n];
        float v1 = W2g[(2 * k2 + 1) * F_OUT + n];
        __nv_bfloat16 h0 = __float2bfloat16(v0), h1 = __float2bfloat16(v1);
        *(uint32_t*)(sm + OFF_WH + (n * SW + 2 * k2) * 2) = packbf(h0, h1);
        *(uint32_t*)(sm + OFF_WL + (n * SW + 2 * k2) * 2) =
            packbf(__float2bfloat16(v0 - __bfloat162float(h0)),
                   __float2bfloat16(v1 - __bfloat162float(h1)));
    }

    float acc[4][NF][4];
#pragma unroll
    for (int mf = 0; mf < 4; mf++)
#pragma unroll
        for (int nf = 0; nf < NF; nf++)
#pragma unroll
            for (int j = 0; j < 4; j++) acc[mf][nf][j] = 0.f;

    const int arow  = tid >> 1;
    const int ahalf = tid & 1;
    const int grow  = rowBase + arow;
    const bool aok  = grow < N_NODES;

    for (int kc = 0; kc < K; kc += KC) {
        {
            const float4* src = (const float4*)&A[(size_t)(aok ? grow : 0) * K + kc + ahalf * 16];
#pragma unroll
            for (int i = 0; i < 4; i++) {
                float4 v = aok ? src[i] : make_float4(0.f, 0.f, 0.f, 0.f);
                __nv_bfloat16 hx = __float2bfloat16(v.x), hy = __float2bfloat16(v.y);
                __nv_bfloat16 hz = __float2bfloat16(v.z), hw = __float2bfloat16(v.w);
                int col = ahalf * 16 + i * 4;
                *(uint32_t*)(sm + OFF_AH + (arow * SA + col) * 2)     = packbf(hx, hy);
                *(uint32_t*)(sm + OFF_AH + (arow * SA + col + 2) * 2) = packbf(hz, hw);
                *(uint32_t*)(sm + OFF_AL + (arow * SA + col) * 2) =
                    packbf(__float2bfloat16(v.x - __bfloat162float(hx)),
                           __float2bfloat16(v.y - __bfloat162float(hy)));
                *(uint32_t*)(sm + OFF_AL + (arow * SA + col + 2) * 2) =
                    packbf(__float2bfloat16(v.z - __bfloat162float(hz)),
                           __float2bfloat16(v.w - __bfloat162float(hw)));
            }
        }
        __syncthreads();

#pragma unroll
        for (int ks = 0; ks < KC / 16; ks++) {
            const int k0 = ks * 16;
            uint32_t bh[NF][2], bl[NF][2];
#pragma unroll
            for (int nf = 0; nf < NF; nf++) {
                int n0 = nw * WN + nf * 8 + (lane >> 2);
                int bc = kc + k0 + (lane & 3) * 2;
                bh[nf][0] = *(const uint32_t*)(sm + OFF_WH + (n0 * SW + bc) * 2);
                bh[nf][1] = *(const uint32_t*)(sm + OFF_WH + (n0 * SW + bc + 8) * 2);
                bl[nf][0] = *(const uint32_t*)(sm + OFF_WL + (n0 * SW + bc) * 2);
                bl[nf][1] = *(const uint32_t*)(sm + OFF_WL + (n0 * SW + bc + 8) * 2);
            }
#pragma unroll
            for (int mf = 0; mf < 4; mf++) {
                int r0 = mw * 64 + mf * 16 + (lane >> 2);
                int ac = k0 + (lane & 3) * 2;
                uint32_t ah[4], al[4];
                ah[0] = *(const uint32_t*)(sm + OFF_AH + ((r0)     * SA + ac) * 2);
                ah[1] = *(const uint32_t*)(sm + OFF_AH + ((r0 + 8) * SA + ac) * 2);
                ah[2] = *(const uint32_t*)(sm + OFF_AH + ((r0)     * SA + ac + 8) * 2);
                ah[3] = *(const uint32_t*)(sm + OFF_AH + ((r0 + 8) * SA + ac + 8) * 2);
                al[0] = *(const uint32_t*)(sm + OFF_AL + ((r0)     * SA + ac) * 2);
                al[1] = *(const uint32_t*)(sm + OFF_AL + ((r0 + 8) * SA + ac) * 2);
                al[2] = *(const uint32_t*)(sm + OFF_AL + ((r0)     * SA + ac + 8) * 2);
                al[3] = *(const uint32_t*)(sm + OFF_AL + ((r0 + 8) * SA + ac + 8) * 2);
#pragma unroll
                for (int nf = 0; nf < NF; nf++) {
                    mma_bf16(acc[mf][nf], ah, bh[nf]);
                    mma_bf16(acc[mf][nf], ah, bl[nf]);
                    mma_bf16(acc[mf][nf], al, bh[nf]);
                }
            }
        }
        __syncthreads();
    }

#pragma unroll
    for (int mf = 0; mf < 4; mf++) {
        int r0 = rowBase + mw * 64 + mf * 16 + (lane >> 2);
        int r1 = r0 + 8;
        float dv0 = (r0 < N_NODES) ? g_dinv[r0] : 0.f;
        float dv1 = (r1 < N_NODES) ? g_dinv[r1] : 0.f;
#pragma unroll
        for (int nf = 0; nf < NF; nf++) {
            int col = nw * WN + nf * 8 + (lane & 3) * 2;
            if (r0 < N_NODES)
                *(__half2*)&g_hs2h[(size_t)r0 * NW + col] =
                    __floats2half2_rn(acc[mf][nf][0] * dv0, acc[mf][nf][1] * dv0);
            if (r1 < N_NODES)
                *(__half2*)&g_hs2h[(size_t)r1 * NW + col] =
                    __floats2half2_rn(acc[mf][nf][2] * dv1, acc[mf][nf][3] * dv1);
        }
    }
}

static constexpr int SMEM_G1 = 2 * (128 * 40 * 2) + 2 * (F_HID * 136 * 2);   // 90112
static constexpr int SMEM_G2 = 2 * (128 * 40 * 2) + 2 * (F_OUT * 136 * 2);   // 55296

struct HxAttr {
    HxAttr() {
        cudaFuncSetAttribute(k_mma1_fill, cudaFuncAttributeMaxDynamicSharedMemorySize, SMEM_G1);
        cudaFuncSetAttribute(k_mma2,      cudaFuncAttributeMaxDynamicSharedMemorySize, SMEM_G2);
    }
};
static HxAttr g_attr;

// ================= aggregation layer 1: fp16 table, range [g_off, g_cur) =================
__global__ void k_agg1(const float* __restrict__ b1) {
    int w    = (blockIdx.x * blockDim.x + threadIdx.x) >> 5;
    int lane = threadIdx.x & 31;
    if (w >= N_NODES) return;
    const uint2* hs = (const uint2*)g_hs1h;
    float4 acc;
    {
        uint2 u = hs[(size_t)w * 32 + lane];
        float2 f0 = __half22float2(*(__half2*)&u.x);
        float2 f1 = __half22float2(*(__half2*)&u.y);
        acc.x = f0.x; acc.y = f0.y; acc.z = f1.x; acc.w = f1.y;
    }
    int e  = g_off[w];
    int e1 = g_cur[w];
    for (; e + 7 < e1; e += 8) {
        int s[8];
#pragma unroll
        for (int q = 0; q < 8; q++) s[q] = g_srcs[e + q];
        uint2 u[8];
#pragma unroll
        for (int q = 0; q < 8; q++) u[q] = hs[(size_t)s[q] * 32 + lane];
#pragma unroll
        for (int q = 0; q < 8; q++) {
            float2 f0 = __half22float2(*(__half2*)&u[q].x);
            float2 f1 = __half22float2(*(__half2*)&u[q].y);
            acc.x += f0.x; acc.y += f0.y; acc.z += f1.x; acc.w += f1.y;
        }
    }
    for (; e < e1; e++) {
        uint2 u = hs[(size_t)g_srcs[e] * 32 + lane];
        float2 f0 = __half22float2(*(__half2*)&u.x);
        float2 f1 = __half22float2(*(__half2*)&u.y);
        acc.x += f0.x; acc.y += f0.y; acc.z += f1.x; acc.w += f1.y;
    }
    float dv = g_dinv[w];
    float4 bb = ((const float4*)b1)[lane];
    float4 o;
    o.x = fmaxf(fmaf(acc.x, dv, bb.x), 0.f);
    o.y = fmaxf(fmaf(acc.y, dv, bb.y), 0.f);
    o.z = fmaxf(fmaf(acc.z, dv, bb.z), 0.f);
    o.w = fmaxf(fmaf(acc.w, dv, bb.w), 0.f);
    ((float4*)g_agg1)[(size_t)w * 32 + lane] = o;
}

// ================= aggregation layer 2: fp16 table, range [g_off, g_cur) =================
__global__ void k_agg2(const float* __restrict__ b2, float* __restrict__ out) {
    int w    = (blockIdx.x * blockDim.x + threadIdx.x) >> 5;
    int lane = threadIdx.x & 31;
    if (w >= N_NODES) return;
    const uint32_t* hs = (const uint32_t*)g_hs2h;
    float2 acc;
    {
        uint32_t u = hs[(size_t)w * 32 + lane];
        acc = __half22float2(*(__half2*)&u);
    }
    int e  = g_off[w];
    int e1 = g_cur[w];
    for (; e + 7 < e1; e += 8) {
        int s[8];
#pragma unroll
        for (int q = 0; q < 8; q++) s[q] = g_srcs[e + q];
        uint32_t u[8];
#pragma unroll
        for (int q = 0; q < 8; q++) u[q] = hs[(size_t)s[q] * 32 + lane];
#pragma unroll
        for (int q = 0; q < 8; q++) {
            float2 f = __half22float2(*(__half2*)&u[q]);
            acc.x += f.x; acc.y += f.y;
        }
    }
    for (; e < e1; e++) {
        uint32_t u = hs[(size_t)g_srcs[e] * 32 + lane];
        float2 f = __half22float2(*(__half2*)&u);
        acc.x += f.x; acc.y += f.y;
    }
    float dv = g_dinv[w];
    float2 bb = ((const float2*)b2)[lane];
    float2 o;
    o.x = fmaf(acc.x, dv, bb.x);
    o.y = fmaf(acc.y, dv, bb.y);
    ((float2*)out)[(size_t)w * 32 + lane] = o;
}

// ================= launcher: 6 kernels, k_agg1 at slot 3 =================
extern "C" void kernel_launch(void* const* d_in, const int* in_sizes, int n_in,
                              void* d_out, int out_size) {
    const float* x  = (const float*)d_in[0];
    const int*   ei = (const int*)d_in[1];
    const float* W1 = (const float*)d_in[2];
    const float* b1 = (const float*)d_in[3];
    const float* W2 = (const float*)d_in[4];
    const float* b2 = (const float*)d_in[5];
    float* out = (float*)d_out;

    k_hist      <<<NB_E4, 256>>>(ei);                    // 0
    k_offsets   <<<NB_N, 256>>>();                       // 1
    k_mma1_fill <<<NB_G, 256, SMEM_G1>>>(x, ei, W1);     // 2  (GEMM1 + fill overlapped)
    k_agg1      <<<(N_NODES + 7) / 8, 256>>>(b1);        // 3  <- ncu capture slot
    k_mma2      <<<NB_G, 256, SMEM_G2>>>(W2);            // 4
    k_agg2      <<<(N_NODES + 7) / 8, 256>>>(b2, out);   // 5
}